// round 7
// baseline (speedup 1.0000x reference)
#include <cuda_runtime.h>
#include <cstdint>
#include <cstddef>

#define NN 50000
#define EE 640000
#define THR2 (0.01f * 0.01f)
#define MAX_IT 10

// ---------------- scratch (__device__ globals) ------------------------------
__device__ float g_base[NN * 512];
__device__ float g_H[NN * 512];
__device__ float g_state[NN * 128];
__device__ float g_new[NN * 128];
__device__ int   g_cnt[NN];
__device__ int   g_ptr_adj[NN + 1];
__device__ int   g_ptr_an[NN + 1];
__device__ int   g_src_adj[EE];
__device__ float g_val_adj[EE];
__device__ int   g_eid_an[EE];
__device__ float g_val_an[EE];
__device__ int   g_flag;
__device__ int   g_done;
__device__ int   g_cont;
__device__ int   g_cmax[640];

// int8 2-digit operands (16B aligned for cp.async)
__device__ __align__(16) signed char g_ws1q1[512 * 576];
__device__ __align__(16) signed char g_ws1q0[512 * 576];
__device__ __align__(16) signed char g_ws2q1[128 * 512];
__device__ __align__(16) signed char g_ws2q0[128 * 512];
__device__ __align__(16) signed char g_wo1q1[512 * 256];
__device__ __align__(16) signed char g_wo1q0[512 * 256];
__device__ float g_sW1[512];
__device__ float g_sW2[128];
__device__ float g_sWo[512];

__device__ __align__(16) signed char g_ndq1[NN * 128];
__device__ __align__(16) signed char g_ndq0[NN * 128];
__device__ __align__(16) signed char g_anq1[NN * 128];
__device__ __align__(16) signed char g_anq0[NN * 128];
__device__ __align__(16) signed char g_aaq1[NN * 64];
__device__ __align__(16) signed char g_aaq0[NN * 64];
__device__ __align__(16) signed char g_stq1[NN * 128];
__device__ __align__(16) signed char g_stq0[NN * 128];
__device__ __align__(16) signed char g_asq1[NN * 128];
__device__ __align__(16) signed char g_asq0[NN * 128];
__device__ __align__(16) signed char g_Hq1[NN * 512];
__device__ __align__(16) signed char g_Hq0[NN * 512];
__device__ float g_sNd[NN];
__device__ float g_sAn[NN];
__device__ float g_sAa[NN];
__device__ float g_sSt[NN];
__device__ float g_sAs[NN];
__device__ float g_sH[NN];

// ---------------- helpers ---------------------------------------------------
#define SWZ(o) ((o) ^ (((o) >> 3) & 0x70))

#define CP16(dst, src, sz) \
    asm volatile("cp.async.cg.shared.global [%0], [%1], 16, %2;" \
                 :: "r"(dst), "l"(src), "r"(sz) : "memory")
#define CP_COMMIT() asm volatile("cp.async.commit_group;" ::: "memory")

#define LDSM4(r0, r1, r2, r3, addr) \
    asm volatile("ldmatrix.sync.aligned.m8n8.x4.shared.b16 {%0,%1,%2,%3}, [%4];" \
                 : "=r"(r0), "=r"(r1), "=r"(r2), "=r"(r3) : "r"(addr))

__device__ __forceinline__ void imma(int* d, const uint32_t* a, const uint32_t* b) {
    asm volatile("mma.sync.aligned.m16n8k32.row.col.s32.s8.s8.s32 "
                 "{%0,%1,%2,%3}, {%4,%5,%6,%7}, {%8,%9}, {%0,%1,%2,%3};"
                 : "+r"(d[0]), "+r"(d[1]), "+r"(d[2]), "+r"(d[3])
                 : "r"(a[0]), "r"(a[1]), "r"(a[2]), "r"(a[3]), "r"(b[0]), "r"(b[1]));
}

__device__ __forceinline__ float fast_tanh(float x) {
    float ax = fabsf(x);
    float e = __expf(-2.f * ax);
    float r = __fdividef(1.f - e, 1.f + e);
    return copysignf(r, x);
}

__device__ __forceinline__ float warp_max(float m) {
    #pragma unroll
    for (int s = 16; s > 0; s >>= 1) m = fmaxf(m, __shfl_xor_sync(0xffffffffu, m, s));
    return m;
}

__device__ __forceinline__ void quant1(float x, float f, int& q1, int& q0) {
    float y = x * f;
    q1 = __float2int_rn(y);
    q0 = __float2int_rn(127.f * (y - (float)q1));
}

__device__ __forceinline__ void quant4(float4 v, float f, uint32_t& p1, uint32_t& p0) {
    int a1, a0, b1, b0, c1, c0, d1, d0;
    quant1(v.x, f, a1, a0); quant1(v.y, f, b1, b0);
    quant1(v.z, f, c1, c0); quant1(v.w, f, d1, d0);
    p1 = (a1 & 0xFF) | ((b1 & 0xFF) << 8) | ((c1 & 0xFF) << 16) | ((uint32_t)(d1 & 0xFF) << 24);
    p0 = (a0 & 0xFF) | ((b0 & 0xFF) << 8) | ((c0 & 0xFF) << 16) | ((uint32_t)(d0 & 0xFF) << 24);
}

// ---------------- CSR build -------------------------------------------------
__global__ void hist_kernel(const int* __restrict__ dst, int e) {
    int i = blockIdx.x * blockDim.x + threadIdx.x;
    if (i < e) atomicAdd(&g_cnt[dst[i]], 1);
}

__global__ void scan_kernel(const int* __restrict__ cnt, int* __restrict__ ptr, int n) {
    __shared__ int sh[1024];
    __shared__ int carry;
    int t = threadIdx.x;
    if (t == 0) { carry = 0; ptr[0] = 0; }
    __syncthreads();
    for (int base = 0; base < n; base += 1024) {
        int x = (base + t < n) ? cnt[base + t] : 0;
        sh[t] = x;
        __syncthreads();
        for (int off = 1; off < 1024; off <<= 1) {
            int y = (t >= off) ? sh[t - off] : 0;
            __syncthreads();
            sh[t] += y;
            __syncthreads();
        }
        if (base + t < n) ptr[base + t + 1] = carry + sh[t];
        __syncthreads();
        if (t == 0) carry += sh[1023];
        __syncthreads();
    }
}

__global__ void scatter_adj_kernel(const int* __restrict__ src, const int* __restrict__ dst,
                                   const float* __restrict__ vals, int e) {
    int i = blockIdx.x * blockDim.x + threadIdx.x;
    if (i < e) {
        int d = dst[i];
        int pos = g_ptr_adj[d] + atomicAdd(&g_cnt[d], 1);
        g_src_adj[pos] = src[i];
        g_val_adj[pos] = vals[i];
    }
}

__global__ void scatter_an_kernel(const int* __restrict__ dst, const float* __restrict__ vals, int e) {
    int i = blockIdx.x * blockDim.x + threadIdx.x;
    if (i < e) {
        int d = dst[i];
        int pos = g_ptr_an[d] + atomicAdd(&g_cnt[d], 1);
        g_eid_an[pos] = i;
        g_val_an[pos] = vals[i];
    }
}

// ---------------- weight quantization ---------------------------------------
__global__ void wcolmax_kernel(const float* __restrict__ W, int K, int N) {
    int idx = blockIdx.x * blockDim.x + threadIdx.x;
    if (idx >= K * N) return;
    int n = idx % N;
    atomicMax(&g_cmax[n], __float_as_int(fabsf(W[idx])));
}

__global__ void wq_write_kernel(const float* __restrict__ W, int K, int N,
                                signed char* __restrict__ q1, signed char* __restrict__ q0,
                                float* __restrict__ sW) {
    int idx = blockIdx.x * blockDim.x + threadIdx.x;
    if (idx >= K * N) return;
    int k = idx / N, n = idx % N;
    float amax = __int_as_float(g_cmax[n]);
    float f = amax > 0.f ? 127.f / amax : 0.f;
    int a1, a0;
    quant1(W[idx], f, a1, a0);
    q1[(size_t)n * K + k] = (signed char)a1;
    q0[(size_t)n * K + k] = (signed char)a0;
    if (k == 0) sW[n] = amax * (1.f / 127.f);
}

// ---------------- A-side quantizers -----------------------------------------
__global__ void quant128_kernel(const float* __restrict__ X, int n,
                                signed char* __restrict__ q1, signed char* __restrict__ q0,
                                float* __restrict__ sc) {
    int w = (blockIdx.x * blockDim.x + threadIdx.x) >> 5;
    int lane = threadIdx.x & 31;
    if (w >= n) return;
    float4 v = *(const float4*)(X + (size_t)w * 128 + lane * 4);
    float m = warp_max(fmaxf(fmaxf(fabsf(v.x), fabsf(v.y)), fmaxf(fabsf(v.z), fabsf(v.w))));
    float f = m > 0.f ? 127.f / m : 0.f;
    uint32_t p1, p0;
    quant4(v, f, p1, p0);
    *(uint32_t*)(q1 + (size_t)w * 128 + lane * 4) = p1;
    *(uint32_t*)(q0 + (size_t)w * 128 + lane * 4) = p0;
    if (lane == 0) sc[w] = m * (1.f / 127.f);
}

__global__ void quant512_kernel(const float* __restrict__ X, int n,
                                signed char* __restrict__ q1, signed char* __restrict__ q0,
                                float* __restrict__ sc, const int* gate) {
    if (gate && *gate == 0) return;
    int w = (blockIdx.x * blockDim.x + threadIdx.x) >> 5;
    int lane = threadIdx.x & 31;
    if (w >= n) return;
    float4 v[4];
    float m = 0.f;
    #pragma unroll
    for (int t = 0; t < 4; t++) {
        v[t] = *(const float4*)(X + (size_t)w * 512 + t * 128 + lane * 4);
        m = fmaxf(m, fmaxf(fmaxf(fabsf(v[t].x), fabsf(v[t].y)), fmaxf(fabsf(v[t].z), fabsf(v[t].w))));
    }
    m = warp_max(m);
    float f = m > 0.f ? 127.f / m : 0.f;
    #pragma unroll
    for (int t = 0; t < 4; t++) {
        uint32_t p1, p0;
        quant4(v[t], f, p1, p0);
        *(uint32_t*)(q1 + (size_t)w * 512 + t * 128 + lane * 4) = p1;
        *(uint32_t*)(q0 + (size_t)w * 512 + t * 128 + lane * 4) = p0;
    }
    if (lane == 0) sc[w] = m * (1.f / 127.f);
}

// ---------------- SPMM (quantized int8 output) ------------------------------
__global__ void spmm128_kernel(const int* __restrict__ ptr, const int* __restrict__ srcs,
                               const float* __restrict__ vals, const float* __restrict__ dense,
                               signed char* __restrict__ q1, signed char* __restrict__ q0,
                               float* __restrict__ sc, int n, const int* gate) {
    if (gate && *gate == 0) return;
    int w = (blockIdx.x * blockDim.x + threadIdx.x) >> 5;
    int lane = threadIdx.x & 31;
    if (w >= n) return;
    int s = ptr[w], t = ptr[w + 1];
    float ax = 0.f, ay = 0.f, az = 0.f, aw = 0.f;
    for (int e = s; e < t; e++) {
        float v = vals[e];
        int src = srcs[e];
        float4 x = *(const float4*)(dense + (size_t)src * 128 + lane * 4);
        ax += v * x.x; ay += v * x.y; az += v * x.z; aw += v * x.w;
    }
    float m = warp_max(fmaxf(fmaxf(fabsf(ax), fabsf(ay)), fmaxf(fabsf(az), fabsf(aw))));
    float f = m > 0.f ? 127.f / m : 0.f;
    uint32_t p1, p0;
    quant4(make_float4(ax, ay, az, aw), f, p1, p0);
    *(uint32_t*)(q1 + (size_t)w * 128 + lane * 4) = p1;
    *(uint32_t*)(q0 + (size_t)w * 128 + lane * 4) = p0;
    if (lane == 0) sc[w] = m * (1.f / 127.f);
}

__global__ void spmm_arcs_kernel(const float* __restrict__ arcs, int n) {
    int w = (blockIdx.x * blockDim.x + threadIdx.x) >> 5;
    int lane = threadIdx.x & 31;
    if (w >= n) return;
    int s = g_ptr_an[w], t = g_ptr_an[w + 1];
    float ax = 0.f, ay = 0.f;
    for (int e = s; e < t; e++) {
        float v = g_val_an[e];
        int eid = g_eid_an[e];
        float2 x = *(const float2*)(arcs + (size_t)eid * 66 + 2 + lane * 2);
        ax += v * x.x; ay += v * x.y;
    }
    float m = warp_max(fmaxf(fabsf(ax), fabsf(ay)));
    float f = m > 0.f ? 127.f / m : 0.f;
    int a1, a0, b1, b0;
    quant1(ax, f, a1, a0);
    quant1(ay, f, b1, b0);
    *(uint16_t*)(g_aaq1 + (size_t)w * 64 + lane * 2) = (uint16_t)((a1 & 0xFF) | ((b1 & 0xFF) << 8));
    *(uint16_t*)(g_aaq0 + (size_t)w * 64 + lane * 2) = (uint16_t)((a0 & 0xFF) | ((b0 & 0xFF) << 8));
    if (lane == 0) g_sAa[w] = m * (1.f / 127.f);
}

// ---------------- state init / convergence / update ------------------------
__global__ void reset_kernel() {
    if (threadIdx.x == 0) { g_flag = 0; g_done = 0; g_cont = 0; }
}

__global__ void init_kernel(const float* __restrict__ si, int n) {
    int w = (blockIdx.x * blockDim.x + threadIdx.x) >> 5;
    int lane = threadIdx.x & 31;
    if (w >= n) return;
    float4 st = *(const float4*)(si + (size_t)w * 128 + lane * 4);
    *(float4*)(g_state + (size_t)w * 128 + lane * 4) = st;
    float m = warp_max(fmaxf(fmaxf(fabsf(st.x), fabsf(st.y)), fmaxf(fabsf(st.z), fabsf(st.w))));
    float f = m > 0.f ? 127.f / m : 0.f;
    uint32_t p1, p0;
    quant4(st, f, p1, p0);
    *(uint32_t*)(g_stq1 + (size_t)w * 128 + lane * 4) = p1;
    *(uint32_t*)(g_stq0 + (size_t)w * 128 + lane * 4) = p0;
    if (lane == 0) g_sSt[w] = m * (1.f / 127.f);
    float dx = st.x - 1.f, dy = st.y - 1.f, dz = st.z - 1.f, dw = st.w - 1.f;
    float d2 = dx * dx + dy * dy + dz * dz + dw * dw;
    #pragma unroll
    for (int s = 16; s > 0; s >>= 1) d2 += __shfl_xor_sync(0xffffffffu, d2, s);
    if (lane == 0 && d2 > THR2 * 128.f) atomicOr(&g_flag, 1);
}

__global__ void finalize_kernel() {
    if (threadIdx.x == 0) {
        int c = (g_flag && !g_done) ? 1 : 0;
        g_cont = c;
        g_done = c ? 0 : 1;
        g_flag = 0;
    }
}

__global__ void update_kernel(int n, const int* gate) {
    if (*gate == 0) return;
    int w = (blockIdx.x * blockDim.x + threadIdx.x) >> 5;
    int lane = threadIdx.x & 31;
    if (w >= n) return;
    float4 st = *(const float4*)(g_state + (size_t)w * 128 + lane * 4);
    float4 nw = *(const float4*)(g_new + (size_t)w * 128 + lane * 4);
    float dx = nw.x - st.x, dy = nw.y - st.y, dz = nw.z - st.z, dw = nw.w - st.w;
    float d2 = dx * dx + dy * dy + dz * dz + dw * dw;
    float n2 = st.x * st.x + st.y * st.y + st.z * st.z + st.w * st.w;
    #pragma unroll
    for (int s = 16; s > 0; s >>= 1) {
        d2 += __shfl_xor_sync(0xffffffffu, d2, s);
        n2 += __shfl_xor_sync(0xffffffffu, n2, s);
    }
    *(float4*)(g_state + (size_t)w * 128 + lane * 4) = nw;
    float m = warp_max(fmaxf(fmaxf(fabsf(nw.x), fabsf(nw.y)), fmaxf(fabsf(nw.z), fabsf(nw.w))));
    float f = m > 0.f ? 127.f / m : 0.f;
    uint32_t p1, p0;
    quant4(nw, f, p1, p0);
    *(uint32_t*)(g_stq1 + (size_t)w * 128 + lane * 4) = p1;
    *(uint32_t*)(g_stq0 + (size_t)w * 128 + lane * 4) = p0;
    if (lane == 0) g_sSt[w] = m * (1.f / 127.f);
    if (lane == 0 && d2 > THR2 * n2) atomicOr(&g_flag, 1);
}

// ---------------- int8 2-digit IMMA GEMM ------------------------------------
// C[M x N] = act( addend + bias + sum_segs dequant(Aq_s) @ dequant(Bq)^T )
// CTA tile 128x64, BK=64 int8, 8 warps (warp 32x32), 2-stage cp.async.
// smem row = 128B: [q1 64B | q0 64B]; A 16KB + B 8KB per stage = 48KB total.
#define GEMM_SMEM 49152

__global__ void __launch_bounds__(256, 1) gemm_i8_kernel(
    int M,
    const signed char* __restrict__ A0q1, const signed char* __restrict__ A0q0,
    const float* __restrict__ sA0, int lda0, int K0, int bofs0,
    const signed char* __restrict__ A1q1, const signed char* __restrict__ A1q0,
    const float* __restrict__ sA1, int lda1, int K1, int bofs1,
    const signed char* __restrict__ A2q1, const signed char* __restrict__ A2q0,
    const float* __restrict__ sA2, int lda2, int K2, int bofs2,
    const signed char* __restrict__ Bq1, const signed char* __restrict__ Bq0,
    const float* __restrict__ sW, int ldb,
    const float* __restrict__ addend, int ldadd,
    const float* __restrict__ bias, int do_tanh,
    float* __restrict__ C, int ldc,
    const int* gate)
{
    if (gate && *gate == 0) return;
    extern __shared__ char smem_raw[];
    const uint32_t sm0 = (uint32_t)__cvta_generic_to_shared(smem_raw);

    const int tid = threadIdx.x;
    const int wid = tid >> 5;
    const int lane = tid & 31;
    const int bm = blockIdx.x * 128;
    const int bn = blockIdx.y * 64;
    const int warp_m = (wid & 3) * 32;
    const int warp_n = (wid >> 2) * 32;

    // A staging: 2 threads/row, halfa selects q1/q0, 4x CP16 (64B)
    const int ra = tid >> 1;
    const int halfa = tid & 1;
    const int growA = bm + ra;
    const bool rowokA = growA < M;
    const int arow = rowokA ? growA : 0;
    // B staging: 4 threads/row, qb: 0,1 -> q1 bytes; 2,3 -> q0; 2x CP16 (32B)
    const int rb = tid >> 2;
    const int qb = tid & 3;

    const signed char* segAq1[3] = {A0q1, A1q1, A2q1};
    const signed char* segAq0[3] = {A0q0, A1q0, A2q0};
    const float* segSA[3] = {sA0, sA1, sA2};
    const int segLda[3] = {lda0, lda1, lda2};
    const int segBofs[3] = {bofs0, bofs1, bofs2};
    const int c0 = K0 / 64;
    const int c01 = c0 + K1 / 64;
    const int total = c01 + K2 / 64;

    int acc11[2][4][4], accX[2][4][4];
    float Df[2][4][4];
    #pragma unroll
    for (int i = 0; i < 2; i++)
        #pragma unroll
        for (int j = 0; j < 4; j++)
            #pragma unroll
            for (int q = 0; q < 4; q++) { acc11[i][j][q] = 0; accX[i][j][q] = 0; Df[i][j][q] = 0.f; }

    float2 swj[4];
    #pragma unroll
    for (int j = 0; j < 4; j++)
        swj[j] = *(const float2*)(sW + bn + warp_n + j * 8 + (lane & 3) * 2);

    auto stage = [&](int ci, int buf) {
        int s, kb;
        if (ci < c0) { s = 0; kb = ci * 64; }
        else if (ci < c01) { s = 1; kb = (ci - c0) * 64; }
        else { s = 2; kb = (ci - c01) * 64; }
        uint32_t ab = sm0 + buf * 24576;
        uint32_t bb = ab + 16384;
        {
            const signed char* src = halfa ? segAq0[s] : segAq1[s];
            const char* g = (const char*)(src + (size_t)arow * segLda[s] + kb);
            uint32_t sz = rowokA ? 16u : 0u;
            #pragma unroll
            for (int c = 0; c < 4; c++) {
                uint32_t dst = ab + SWZ((uint32_t)(ra * 128 + halfa * 64 + c * 16));
                CP16(dst, g + c * 16, sz);
            }
        }
        {
            const signed char* src = (qb < 2) ? Bq1 : Bq0;
            const char* g = (const char*)(src + (size_t)(bn + rb) * ldb + segBofs[s] + kb + (qb & 1) * 32);
            #pragma unroll
            for (int c = 0; c < 2; c++) {
                uint32_t dst = bb + SWZ((uint32_t)(rb * 128 + (qb >= 2 ? 64 : 0) + (qb & 1) * 32 + c * 16));
                CP16(dst, g + c * 16, 16u);
            }
        }
        CP_COMMIT();
    };

    stage(0, 0);
    for (int ci = 0; ci < total; ci++) {
        int buf = ci & 1;
        bool hasnext = (ci + 1) < total;
        if (hasnext) stage(ci + 1, buf ^ 1);
        if (hasnext) asm volatile("cp.async.wait_group 1;" ::: "memory");
        else asm volatile("cp.async.wait_group 0;" ::: "memory");
        __syncthreads();

        uint32_t ab = sm0 + buf * 24576;
        uint32_t bb = ab + 16384;
        #pragma unroll
        for (int ks = 0; ks < 2; ks++) {
            uint32_t aq1[2][4], aq0[2][4], b1f[4][2], b0f[4][2];
            #pragma unroll
            for (int i = 0; i < 2; i++) {
                uint32_t rowA = warp_m + i * 16 + (lane & 7) + ((lane >> 3) & 1) * 8;
                uint32_t co = ks * 32 + (lane >> 4) * 16;
                LDSM4(aq1[i][0], aq1[i][1], aq1[i][2], aq1[i][3], ab + SWZ(rowA * 128 + co));
                LDSM4(aq0[i][0], aq0[i][1], aq0[i][2], aq0[i][3], ab + SWZ(rowA * 128 + 64 + co));
            }
            #pragma unroll
            for (int jp = 0; jp < 2; jp++) {
                uint32_t rowB = warp_n + jp * 16 + (lane & 7) + (lane >> 4) * 8;
                uint32_t co = ks * 32 + ((lane >> 3) & 1) * 16;
                uint32_t t0, t1, t2, t3;
                LDSM4(t0, t1, t2, t3, bb + SWZ(rowB * 128 + co));
                b1f[2 * jp][0] = t0; b1f[2 * jp][1] = t1;
                b1f[2 * jp + 1][0] = t2; b1f[2 * jp + 1][1] = t3;
                LDSM4(t0, t1, t2, t3, bb + SWZ(rowB * 128 + 64 + co));
                b0f[2 * jp][0] = t0; b0f[2 * jp][1] = t1;
                b0f[2 * jp + 1][0] = t2; b0f[2 * jp + 1][1] = t3;
            }
            #pragma unroll
            for (int i = 0; i < 2; i++)
                #pragma unroll
                for (int j = 0; j < 4; j++)
                    imma(acc11[i][j], aq1[i], b1f[j]);
            #pragma unroll
            for (int i = 0; i < 2; i++)
                #pragma unroll
                for (int j = 0; j < 4; j++)
                    imma(accX[i][j], aq1[i], b0f[j]);
            #pragma unroll
            for (int i = 0; i < 2; i++)
                #pragma unroll
                for (int j = 0; j < 4; j++)
                    imma(accX[i][j], aq0[i], b1f[j]);
        }
        __syncthreads();

        int sThis = (ci < c0) ? 0 : (ci < c01) ? 1 : 2;
        int sNext = hasnext ? (((ci + 1) < c0) ? 0 : ((ci + 1) < c01) ? 1 : 2) : -1;
        if (sNext != sThis) {
            const float* sAp = segSA[sThis];
            float sar[4];
            #pragma unroll
            for (int t = 0; t < 4; t++) {
                int row = bm + warp_m + (lane >> 2) + t * 8;
                sar[t] = (row < M) ? sAp[row] : 0.f;
            }
            #pragma unroll
            for (int i = 0; i < 2; i++)
                #pragma unroll
                for (int j = 0; j < 4; j++)
                    #pragma unroll
                    for (int q = 0; q < 4; q++) {
                        float sa = sar[i * 2 + (q >> 1)];
                        float sw = (q & 1) ? swj[j].y : swj[j].x;
                        Df[i][j][q] += sa * sw *
                            ((float)acc11[i][j][q] + (float)accX[i][j][q] * (1.f / 127.f));
                        acc11[i][j][q] = 0;
                        accX[i][j][q] = 0;
                    }
        }
    }

    // epilogue
    const int gr = lane >> 2;
    const int gc = (lane & 3) * 2;
    #pragma unroll
    for (int i = 0; i < 2; i++) {
        #pragma unroll
        for (int hf = 0; hf < 2; hf++) {
            int row = bm + warp_m + i * 16 + hf * 8 + gr;
            if (row >= M) continue;
            #pragma unroll
            for (int j = 0; j < 4; j++) {
                int col = bn + warp_n + j * 8 + gc;
                float vx = Df[i][j][hf * 2 + 0];
                float vy = Df[i][j][hf * 2 + 1];
                if (addend) {
                    float2 b = *(const float2*)(addend + (size_t)row * ldadd + col);
                    vx += b.x; vy += b.y;
                }
                if (bias) {
                    float2 b = *(const float2*)(bias + col);
                    vx += b.x; vy += b.y;
                }
                if (do_tanh) { vx = fast_tanh(vx); vy = fast_tanh(vy); }
                float2 o; o.x = vx; o.y = vy;
                *(float2*)(C + (size_t)row * ldc + col) = o;
            }
        }
    }
}

// ---------------- final projection (N x 512 @ 512 x 7) ----------------------
__global__ void out_kernel(const float* __restrict__ Hout, const float* __restrict__ Wo2,
                           const float* __restrict__ bo2, const int* __restrict__ m1,
                           const int* __restrict__ m2, float* __restrict__ out, int n) {
    __shared__ float w[512 * 7];
    for (int i = threadIdx.x; i < 512 * 7; i += blockDim.x) w[i] = Wo2[i];
    __syncthreads();
    int wrp = (blockIdx.x * blockDim.x + threadIdx.x) >> 5;
    int lane = threadIdx.x & 31;
    if (wrp >= n) return;
    const float* h = Hout + (size_t)wrp * 512;
    float acc[7] = {0.f, 0.f, 0.f, 0.f, 0.f, 0.f, 0.f};
    for (int t = 0; t < 16; t++) {
        int k = t * 32 + lane;
        float x = h[k];
        #pragma unroll
        for (int o = 0; o < 7; o++) acc[o] += x * w[k * 7 + o];
    }
    #pragma unroll
    for (int o = 0; o < 7; o++) {
        #pragma unroll
        for (int s = 16; s > 0; s >>= 1) acc[o] += __shfl_xor_sync(0xffffffffu, acc[o], s);
    }
    if (lane == 0) {
        float mk = (m1[wrp] != 0 && m2[wrp] != 0) ? 1.f : 0.f;
        #pragma unroll
        for (int o = 0; o < 7; o++) out[(size_t)wrp * 7 + o] = (acc[o] + bo2[o]) * mk;
    }
}

// ---------------- host ------------------------------------------------------
extern "C" void kernel_launch(void* const* d_in, const int* in_sizes, int n_in,
                              void* d_out, int out_size) {
    const float* nodes       = (const float*)d_in[0];
    const float* arcs        = (const float*)d_in[1];
    const int*   set_mask    = (const int*)d_in[2];
    const int*   output_mask = (const int*)d_in[3];
    const int*   adj_src     = (const int*)d_in[4];
    const int*   adj_dst     = (const int*)d_in[5];
    const float* adj_vals    = (const float*)d_in[6];
    const int*   an_dst      = (const int*)d_in[7];
    const float* an_vals     = (const float*)d_in[8];
    const float* state_init  = (const float*)d_in[9];
    const float* Ws1         = (const float*)d_in[10];
    const float* bs1         = (const float*)d_in[11];
    const float* Ws2         = (const float*)d_in[12];
    const float* bs2         = (const float*)d_in[13];
    const float* Wo1         = (const float*)d_in[14];
    const float* bo1         = (const float*)d_in[15];
    const float* Wo2         = (const float*)d_in[16];
    const float* bo2         = (const float*)d_in[17];

    const int n = NN;
    const int e = EE;

    float *p_base, *p_H, *p_state, *p_new, *p_val_adj;
    int *p_cnt, *p_ptr_adj, *p_ptr_an, *p_src_adj, *p_cont, *p_cmax;
    signed char *p_ws1q1, *p_ws1q0, *p_ws2q1, *p_ws2q0, *p_wo1q1, *p_wo1q0;
    signed char *p_ndq1, *p_ndq0, *p_anq1, *p_anq0, *p_stq1, *p_stq0;
    signed char *p_asq1, *p_asq0, *p_aaq1, *p_aaq0, *p_Hq1, *p_Hq0;
    float *p_sW1, *p_sW2, *p_sWo, *p_sNd, *p_sAn, *p_sAa, *p_sSt, *p_sAs, *p_sH;
    cudaGetSymbolAddress((void**)&p_base, g_base);
    cudaGetSymbolAddress((void**)&p_H, g_H);
    cudaGetSymbolAddress((void**)&p_state, g_state);
    cudaGetSymbolAddress((void**)&p_new, g_new);
    cudaGetSymbolAddress((void**)&p_cnt, g_cnt);
    cudaGetSymbolAddress((void**)&p_ptr_adj, g_ptr_adj);
    cudaGetSymbolAddress((void**)&p_ptr_an, g_ptr_an);
    cudaGetSymbolAddress((void**)&p_src_adj, g_src_adj);
    cudaGetSymbolAddress((void**)&p_val_adj, g_val_adj);
    cudaGetSymbolAddress((void**)&p_cont, g_cont);
    cudaGetSymbolAddress((void**)&p_cmax, g_cmax);
    cudaGetSymbolAddress((void**)&p_ws1q1, g_ws1q1);
    cudaGetSymbolAddress((void**)&p_ws1q0, g_ws1q0);
    cudaGetSymbolAddress((void**)&p_ws2q1, g_ws2q1);
    cudaGetSymbolAddress((void**)&p_ws2q0, g_ws2q0);
    cudaGetSymbolAddress((void**)&p_wo1q1, g_wo1q1);
    cudaGetSymbolAddress((void**)&p_wo1q0, g_wo1q0);
    cudaGetSymbolAddress((void**)&p_ndq1, g_ndq1);
    cudaGetSymbolAddress((void**)&p_ndq0, g_ndq0);
    cudaGetSymbolAddress((void**)&p_anq1, g_anq1);
    cudaGetSymbolAddress((void**)&p_anq0, g_anq0);
    cudaGetSymbolAddress((void**)&p_aaq1, g_aaq1);
    cudaGetSymbolAddress((void**)&p_aaq0, g_aaq0);
    cudaGetSymbolAddress((void**)&p_stq1, g_stq1);
    cudaGetSymbolAddress((void**)&p_stq0, g_stq0);
    cudaGetSymbolAddress((void**)&p_asq1, g_asq1);
    cudaGetSymbolAddress((void**)&p_asq0, g_asq0);
    cudaGetSymbolAddress((void**)&p_Hq1, g_Hq1);
    cudaGetSymbolAddress((void**)&p_Hq0, g_Hq0);
    cudaGetSymbolAddress((void**)&p_sW1, g_sW1);
    cudaGetSymbolAddress((void**)&p_sW2, g_sW2);
    cudaGetSymbolAddress((void**)&p_sWo, g_sWo);
    cudaGetSymbolAddress((void**)&p_sNd, g_sNd);
    cudaGetSymbolAddress((void**)&p_sAn, g_sAn);
    cudaGetSymbolAddress((void**)&p_sAa, g_sAa);
    cudaGetSymbolAddress((void**)&p_sSt, g_sSt);
    cudaGetSymbolAddress((void**)&p_sAs, g_sAs);
    cudaGetSymbolAddress((void**)&p_sH, g_sH);

    cudaFuncSetAttribute(gemm_i8_kernel, cudaFuncAttributeMaxDynamicSharedMemorySize, GEMM_SMEM);

    const int gbE = (e + 255) / 256;
    const int gbW = (n * 32 + 255) / 256;
    const int gbM = (n + 127) / 128;

    // ---- one-time weight quantization (colmax -> 2-digit int8, transposed) ----
    cudaMemsetAsync(p_cmax, 0, 640 * sizeof(int));
    wcolmax_kernel<<<(576 * 512 + 255) / 256, 256>>>(Ws1, 576, 512);
    wq_write_kernel<<<(576 * 512 + 255) / 256, 256>>>(Ws1, 576, 512, p_ws1q1, p_ws1q0, p_sW1);
    cudaMemsetAsync(p_cmax, 0, 640 * sizeof(int));
    wcolmax_kernel<<<(512 * 128 + 255) / 256, 256>>>(Ws2, 512, 128);
    wq_write_kernel<<<(512 * 128 + 255) / 256, 256>>>(Ws2, 512, 128, p_ws2q1, p_ws2q0, p_sW2);
    cudaMemsetAsync(p_cmax, 0, 640 * sizeof(int));
    wcolmax_kernel<<<(256 * 512 + 255) / 256, 256>>>(Wo1, 256, 512);
    wq_write_kernel<<<(256 * 512 + 255) / 256, 256>>>(Wo1, 256, 512, p_wo1q1, p_wo1q0, p_sWo);

    // nodes features -> int8 digits
    quant128_kernel<<<gbW, 256>>>(nodes, n, p_ndq1, p_ndq0, p_sNd);

    // ---- CSR builds ----
    cudaMemsetAsync(p_cnt, 0, n * sizeof(int));
    hist_kernel<<<gbE, 256>>>(an_dst, e);
    scan_kernel<<<1, 1024>>>(p_cnt, p_ptr_an, n);
    cudaMemsetAsync(p_cnt, 0, n * sizeof(int));
    scatter_an_kernel<<<gbE, 256>>>(an_dst, an_vals, e);

    cudaMemsetAsync(p_cnt, 0, n * sizeof(int));
    hist_kernel<<<gbE, 256>>>(adj_dst, e);
    scan_kernel<<<1, 1024>>>(p_cnt, p_ptr_adj, n);
    cudaMemsetAsync(p_cnt, 0, n * sizeof(int));
    scatter_adj_kernel<<<gbE, 256>>>(adj_src, adj_dst, adj_vals, e);

    // ---- loop-invariant aggregations (quantized outputs) ----
    spmm_arcs_kernel<<<gbW, 256>>>(arcs, n);
    spmm128_kernel<<<gbW, 256>>>(p_ptr_adj, p_src_adj, p_val_adj, nodes, p_anq1, p_anq0, p_sAn, n, nullptr);

    // ---- state init + invariant part of GEMM1 ----
    reset_kernel<<<1, 32>>>();
    init_kernel<<<gbW, 256>>>(state_init, n);
    gemm_i8_kernel<<<dim3(gbM, 8), 256, GEMM_SMEM>>>(
        n,
        p_ndq1, p_ndq0, p_sNd, 128, 128, 128,
        p_anq1, p_anq0, p_sAn, 128, 128, 384,
        p_aaq1, p_aaq0, p_sAa, 64, 64, 512,
        p_ws1q1, p_ws1q0, p_sW1, 576,
        nullptr, 0, bs1, 0,
        p_base, 512, nullptr);

    // ---- fixed-point iterations ----
    for (int it = 0; it < MAX_IT; it++) {
        finalize_kernel<<<1, 32>>>();
        spmm128_kernel<<<gbW, 256>>>(p_ptr_adj, p_src_adj, p_val_adj, p_state, p_asq1, p_asq0, p_sAs, n, p_cont);
        gemm_i8_kernel<<<dim3(gbM, 8), 256, GEMM_SMEM>>>(
            n,
            p_stq1, p_stq0, p_sSt, 128, 128, 0,
            p_asq1, p_asq0, p_sAs, 128, 128, 256,
            nullptr, nullptr, nullptr, 0, 0, 0,
            p_ws1q1, p_ws1q0, p_sW1, 576,
            p_base, 512, nullptr, 1,
            p_H, 512, p_cont);
        quant512_kernel<<<gbW, 256>>>(p_H, n, p_Hq1, p_Hq0, p_sH, p_cont);
        gemm_i8_kernel<<<dim3(gbM, 2), 256, GEMM_SMEM>>>(
            n,
            p_Hq1, p_Hq0, p_sH, 512, 512, 0,
            nullptr, nullptr, nullptr, 0, 0, 0,
            nullptr, nullptr, nullptr, 0, 0, 0,
            p_ws2q1, p_ws2q0, p_sW2, 512,
            nullptr, 0, bs2, 1,
            p_new, 128, p_cont);
        update_kernel<<<gbW, 256>>>(n, p_cont);
    }

    // ---- output head ----
    gemm_i8_kernel<<<dim3(gbM, 8), 256, GEMM_SMEM>>>(
        n,
        p_stq1, p_stq0, p_sSt, 128, 128, 0,
        p_ndq1, p_ndq0, p_sNd, 128, 128, 128,
        nullptr, nullptr, nullptr, 0, 0, 0,
        p_wo1q1, p_wo1q0, p_sWo, 256,
        nullptr, 0, bo1, 1,
        p_H, 512, nullptr);
    out_kernel<<<gbW, 256>>>(p_H, Wo2, bo2, set_mask, output_mask, (float*)d_out, n);
}